// round 13
// baseline (speedup 1.0000x reference)
#include <cuda_runtime.h>
#include <cstdint>

// Problem constants (B=32, T=512, F=513, S=3)
#define BB        32
#define NPB       262656            // triples per batch
#define NQUADS    65664             // NPB/4: quads (4 triples = 48B) per batch
#define BLKX      16                // blocks per batch
#define NBLK      (BB * BLKX)       // 512 CTAs
#define NTHR      256
#define QPB       (NQUADS / BLKX)   // 4104 quads per block
#define QPS       114               // quads per stage (one per consuming thread)
#define NSTAGES   (QPB / QPS)       // 36, exact
#define NSLOTS    4                 // ring depth
#define STAGE_B   (QPS * 48)        // 5472 bytes per array per stage
#define STAGE_F4  (QPS * 3)         // 342 float4 per array per stage

typedef unsigned long long u64;

// Cost-matrix accumulators + hierarchical completion counters.
// Zero at static init; finisher re-zeroes everything -> graph-replay safe.
__device__ float g_C[BB * 9];
__device__ unsigned int g_cnt_b[BB];
__device__ unsigned int g_cnt;

__device__ __forceinline__ uint32_t smem_u32(const void* p) {
    uint32_t a;
    asm("{ .reg .u64 t; cvta.to.shared.u64 t, %1; cvt.u32.u64 %0, t; }" : "=r"(a) : "l"(p));
    return a;
}
__device__ __forceinline__ u64 pack2(float lo, float hi) {
    u64 r; asm("mov.b64 %0, {%1, %2};" : "=l"(r) : "f"(lo), "f"(hi)); return r;
}
__device__ __forceinline__ void unpack2(float& lo, float& hi, u64 a) {
    asm("mov.b64 {%0, %1}, %2;" : "=f"(lo), "=f"(hi) : "l"(a));
}
__device__ __forceinline__ u64 sub2(u64 a, u64 b) {
    u64 r; asm("sub.rn.f32x2 %0, %1, %2;" : "=l"(r) : "l"(a), "l"(b)); return r;
}
__device__ __forceinline__ u64 add2(u64 a, u64 b) {
    u64 r; asm("add.rn.f32x2 %0, %1, %2;" : "=l"(r) : "l"(a), "l"(b)); return r;
}
__device__ __forceinline__ u64 abs2(u64 a) { return a & 0x7FFFFFFF7FFFFFFFULL; }

__device__ __forceinline__ void mbar_init(uint32_t mbar, uint32_t cnt) {
    asm volatile("mbarrier.init.shared.b64 [%0], %1;" :: "r"(mbar), "r"(cnt) : "memory");
}
__device__ __forceinline__ void mbar_expect_tx(uint32_t mbar, uint32_t bytes) {
    asm volatile("mbarrier.arrive.expect_tx.shared.b64 _, [%0], %1;"
                 :: "r"(mbar), "r"(bytes) : "memory");
}
__device__ __forceinline__ void mbar_arrive(uint32_t mbar) {
    asm volatile("mbarrier.arrive.release.cta.shared.b64 _, [%0];"
                 :: "r"(mbar) : "memory");
}
__device__ __forceinline__ void tma_bulk_1d(uint32_t smem_dst, const void* gmem_src,
                                            uint32_t bytes, uint32_t mbar) {
    asm volatile("cp.async.bulk.shared::cluster.global.mbarrier::complete_tx::bytes "
                 "[%0], [%1], %2, [%3];"
                 :: "r"(smem_dst), "l"(gmem_src), "r"(bytes), "r"(mbar) : "memory");
}
__device__ __forceinline__ void mbar_wait(uint32_t mbar, uint32_t parity) {
    asm volatile(
        "{\n\t"
        ".reg .pred P;\n\t"
        "WAIT_%=:\n\t"
        "mbarrier.try_wait.parity.acquire.cta.shared::cta.b64 P, [%0], %1, 0x989680;\n\t"
        "@P bra.uni DONE_%=;\n\t"
        "bra.uni WAIT_%=;\n\t"
        "DONE_%=:\n\t"
        "}"
        :: "r"(mbar), "r"(parity) : "memory");
}

// Accumulate one 12-float quad (3 float4 per array) into acc[9].
__device__ __forceinline__ void accum_chunk(
    u64* acc,
    const float4 e0, const float4 e1, const float4 e2,
    const float4 t0, const float4 t1, const float4 t2)
{
    const u64 EA0 = pack2(e0.x, e0.w), EA1 = pack2(e0.y, e1.x), EA2 = pack2(e0.z, e1.y);
    const u64 TA0 = pack2(t0.x, t0.w), TA1 = pack2(t0.y, t1.x), TA2 = pack2(t0.z, t1.y);
    const u64 EB0 = pack2(e1.z, e2.y), EB1 = pack2(e1.w, e2.z), EB2 = pack2(e2.x, e2.w);
    const u64 TB0 = pack2(t1.z, t2.y), TB1 = pack2(t1.w, t2.z), TB2 = pack2(t2.x, t2.w);

    acc[0] = add2(acc[0], abs2(sub2(EA0, TA0)));
    acc[1] = add2(acc[1], abs2(sub2(EA0, TA1)));
    acc[2] = add2(acc[2], abs2(sub2(EA0, TA2)));
    acc[3] = add2(acc[3], abs2(sub2(EA1, TA0)));
    acc[4] = add2(acc[4], abs2(sub2(EA1, TA1)));
    acc[5] = add2(acc[5], abs2(sub2(EA1, TA2)));
    acc[6] = add2(acc[6], abs2(sub2(EA2, TA0)));
    acc[7] = add2(acc[7], abs2(sub2(EA2, TA1)));
    acc[8] = add2(acc[8], abs2(sub2(EA2, TA2)));

    acc[0] = add2(acc[0], abs2(sub2(EB0, TB0)));
    acc[1] = add2(acc[1], abs2(sub2(EB0, TB1)));
    acc[2] = add2(acc[2], abs2(sub2(EB0, TB2)));
    acc[3] = add2(acc[3], abs2(sub2(EB1, TB0)));
    acc[4] = add2(acc[4], abs2(sub2(EB1, TB1)));
    acc[5] = add2(acc[5], abs2(sub2(EB1, TB2)));
    acc[6] = add2(acc[6], abs2(sub2(EB2, TB0)));
    acc[7] = add2(acc[7], abs2(sub2(EB2, TB1)));
    acc[8] = add2(acc[8], abs2(sub2(EB2, TB2)));
}

__global__ void __launch_bounds__(NTHR) pil_tma_kernel(
    const float* __restrict__ est, const float* __restrict__ tgt,
    float* __restrict__ out)
{
    // 4-slot ring of SMEM tiles. 4 x 2 x 5472 = 43776 B.
    __shared__ __align__(128) float4 s_e[NSLOTS][STAGE_F4];
    __shared__ __align__(128) float4 s_t[NSLOTS][STAGE_F4];
    __shared__ __align__(8) unsigned long long s_full[NSLOTS];
    __shared__ __align__(8) unsigned long long s_empty[NSLOTS];

    const int tid = threadIdx.x;
    const int b = blockIdx.x >> 4;        // batch
    const int x = blockIdx.x & 15;        // block-in-batch

    uint32_t full[NSLOTS], empty[NSLOTS], se[NSLOTS], st[NSLOTS];
#pragma unroll
    for (int s = 0; s < NSLOTS; s++) {
        full[s]  = smem_u32(&s_full[s]);
        empty[s] = smem_u32(&s_empty[s]);
        se[s]    = smem_u32(&s_e[s][0]);
        st[s]    = smem_u32(&s_t[s][0]);
    }

    if (tid == 0) {
#pragma unroll
        for (int s = 0; s < NSLOTS; s++) {
            mbar_init(full[s], 1);      // tx-based completion
            mbar_init(empty[s], QPS);   // one arrive per consuming thread
        }
    }
    __syncthreads();
    asm volatile("fence.proxy.async.shared::cta;" ::: "memory");

    // This block's contiguous slice: QPB quads starting at x*QPB.
    const char* ge = (const char*)est + (size_t)b * NPB * 12 + (size_t)x * QPB * 48;
    const char* gt = (const char*)tgt + (size_t)b * NPB * 12 + (size_t)x * QPB * 48;

    // Prologue: fill slots 0..2 (3 stages ahead).
    if (tid == 0) {
#pragma unroll
        for (int k = 0; k < 3; k++) {
            mbar_expect_tx(full[k], 2 * STAGE_B);
            tma_bulk_1d(se[k], ge + (size_t)k * STAGE_B, STAGE_B, full[k]);
            tma_bulk_1d(st[k], gt + (size_t)k * STAGE_B, STAGE_B, full[k]);
        }
    }

    u64 acc[9];
#pragma unroll
    for (int q = 0; q < 9; q++) acc[q] = 0ULL;

    for (int i = 0; i < NSTAGES; i++) {
        const int s = i & 3;

        // Producer: issue stage i+3 into its (just-freed) slot.
        if (tid == 0) {
            const int k = i + 3;
            if (k < NSTAGES) {
                const int s3 = k & 3;
                if (k >= NSLOTS)
                    mbar_wait(empty[s3], ((k >> 2) - 1) & 1);  // consumers freed slot
                mbar_expect_tx(full[s3], 2 * STAGE_B);
                tma_bulk_1d(se[s3], ge + (size_t)k * STAGE_B, STAGE_B, full[s3]);
                tma_bulk_1d(st[s3], gt + (size_t)k * STAGE_B, STAGE_B, full[s3]);
            }
        }

        // Consumers: threads 0..QPS-1 each take one quad.
        if (tid < QPS) {
            mbar_wait(full[s], (i >> 2) & 1);
            const float4* be = &s_e[s][3 * tid];
            const float4* bt = &s_t[s][3 * tid];
            accum_chunk(acc, be[0], be[1], be[2], bt[0], bt[1], bt[2]);
            mbar_arrive(empty[s]);
        }
    }

    // Collapse packed halves.
    float a[9];
#pragma unroll
    for (int q = 0; q < 9; q++) {
        float lo, hi;
        unpack2(lo, hi, acc[q]);
        a[q] = lo + hi;
    }

    // Warp reduction (idle warps contribute zeros).
#pragma unroll
    for (int off = 16; off > 0; off >>= 1) {
#pragma unroll
        for (int q = 0; q < 9; q++)
            a[q] += __shfl_down_sync(0xFFFFFFFFu, a[q], off);
    }

    // Block reduction across 8 warps.
    __shared__ float s_part[NTHR / 32][9];
    const int lane = tid & 31;
    const int warp = tid >> 5;
    if (lane == 0) {
#pragma unroll
        for (int q = 0; q < 9; q++) s_part[warp][q] = a[q];
    }
    __syncthreads();

    if (tid < 9) {
        float s = 0.0f;
#pragma unroll
        for (int w = 0; w < NTHR / 32; w++) s += s_part[w][tid];
        atomicAdd(&g_C[b * 9 + tid], s);
    }

    // ---- hierarchical last-block-done ----
    __shared__ unsigned int s_islast;
    __threadfence();
    if (tid == 0) {
        s_islast = 0;
        if (atomicAdd(&g_cnt_b[b], 1u) == BLKX - 1) {
            __threadfence();
            s_islast = (atomicAdd(&g_cnt, 1u) == BB - 1);
        }
    }
    __syncthreads();
    if (!s_islast) return;

    // ---- finisher: permutation-min epilogue ----
    __shared__ float sC[BB * 9];
    for (int ent = tid; ent < BB * 9; ent += NTHR)
        sC[ent] = __ldcg(&g_C[ent]) * (1.0f / (float)NPB);
    __syncthreads();

    if (tid < 32) {
        const float* c = &sC[tid * 9];
        float best = c[0] + c[4] + c[8];
        best = fminf(best, c[0] + c[7] + c[5]);
        best = fminf(best, c[3] + c[1] + c[8]);
        best = fminf(best, c[3] + c[7] + c[2]);
        best = fminf(best, c[6] + c[1] + c[5]);
        best = fminf(best, c[6] + c[4] + c[2]);
        best *= (1.0f / 3.0f);

#pragma unroll
        for (int off = 16; off > 0; off >>= 1)
            best += __shfl_down_sync(0xFFFFFFFFu, best, off);

        if (tid == 0) out[0] = best * (1.0f / (float)BB);
    }
    __syncthreads();

    // Reset ALL scratch for the next graph replay.
    for (int ent = tid; ent < BB * 9; ent += NTHR) g_C[ent] = 0.0f;
    if (tid < BB) g_cnt_b[tid] = 0u;
    if (tid == 0) g_cnt = 0u;
}

extern "C" void kernel_launch(void* const* d_in, const int* in_sizes, int n_in,
                              void* d_out, int out_size) {
    const float* est = (const float*)d_in[0];
    const float* tgt = (const float*)d_in[1];
    float* out = (float*)d_out;

    pil_tma_kernel<<<NBLK, NTHR>>>(est, tgt, out);
}

// round 14
// speedup vs baseline: 1.3333x; 1.3333x over previous
#include <cuda_runtime.h>
#include <cstdint>

// Problem constants (B=32, T=512, F=513, S=3)
#define BB        32
#define NPB       262656            // triples per batch
#define NQUADS    65664             // NPB/4: quads (4 triples = 48B) per batch
#define BLKX      16                // blocks per batch
#define NBLK      (BB * BLKX)       // 512 CTAs
#define NTHR      256
#define QPB       (NQUADS / BLKX)   // 4104 quads per block
#define QPS       152               // quads per stage
#define NSTAGES   (QPB / QPS)       // 27, exact
#define NSLOTS    3                 // ring depth
#define STAGE_B   (QPS * 48)        // 7296 bytes per array per stage
#define STAGE_F4  (QPS * 3)         // 456 float4 per array per stage

typedef unsigned long long u64;

// Cost-matrix accumulators + hierarchical completion counters.
// Zero at static init; finisher re-zeroes everything -> graph-replay safe.
__device__ float g_C[BB * 9];
__device__ unsigned int g_cnt_b[BB];
__device__ unsigned int g_cnt;

__device__ __forceinline__ uint32_t smem_u32(const void* p) {
    uint32_t a;
    asm("{ .reg .u64 t; cvta.to.shared.u64 t, %1; cvt.u32.u64 %0, t; }" : "=r"(a) : "l"(p));
    return a;
}
__device__ __forceinline__ u64 pack2(float lo, float hi) {
    u64 r; asm("mov.b64 %0, {%1, %2};" : "=l"(r) : "f"(lo), "f"(hi)); return r;
}
__device__ __forceinline__ void unpack2(float& lo, float& hi, u64 a) {
    asm("mov.b64 {%0, %1}, %2;" : "=f"(lo), "=f"(hi) : "l"(a));
}
__device__ __forceinline__ u64 sub2(u64 a, u64 b) {
    u64 r; asm("sub.rn.f32x2 %0, %1, %2;" : "=l"(r) : "l"(a), "l"(b)); return r;
}
__device__ __forceinline__ u64 add2(u64 a, u64 b) {
    u64 r; asm("add.rn.f32x2 %0, %1, %2;" : "=l"(r) : "l"(a), "l"(b)); return r;
}
__device__ __forceinline__ u64 abs2(u64 a) { return a & 0x7FFFFFFF7FFFFFFFULL; }

__device__ __forceinline__ void mbar_init(uint32_t mbar, uint32_t cnt) {
    asm volatile("mbarrier.init.shared.b64 [%0], %1;" :: "r"(mbar), "r"(cnt) : "memory");
}
__device__ __forceinline__ void mbar_expect_tx(uint32_t mbar, uint32_t bytes) {
    asm volatile("mbarrier.arrive.expect_tx.shared.b64 _, [%0], %1;"
                 :: "r"(mbar), "r"(bytes) : "memory");
}
__device__ __forceinline__ void tma_bulk_1d(uint32_t smem_dst, const void* gmem_src,
                                            uint32_t bytes, uint32_t mbar) {
    asm volatile("cp.async.bulk.shared::cluster.global.mbarrier::complete_tx::bytes "
                 "[%0], [%1], %2, [%3];"
                 :: "r"(smem_dst), "l"(gmem_src), "r"(bytes), "r"(mbar) : "memory");
}
__device__ __forceinline__ void mbar_wait(uint32_t mbar, uint32_t parity) {
    asm volatile(
        "{\n\t"
        ".reg .pred P;\n\t"
        "WAIT_%=:\n\t"
        "mbarrier.try_wait.parity.acquire.cta.shared::cta.b64 P, [%0], %1, 0x989680;\n\t"
        "@P bra.uni DONE_%=;\n\t"
        "bra.uni WAIT_%=;\n\t"
        "DONE_%=:\n\t"
        "}"
        :: "r"(mbar), "r"(parity) : "memory");
}

// Accumulate one 12-float quad (3 float4 per array) into acc[9].
__device__ __forceinline__ void accum_chunk(
    u64* acc,
    const float4 e0, const float4 e1, const float4 e2,
    const float4 t0, const float4 t1, const float4 t2)
{
    const u64 EA0 = pack2(e0.x, e0.w), EA1 = pack2(e0.y, e1.x), EA2 = pack2(e0.z, e1.y);
    const u64 TA0 = pack2(t0.x, t0.w), TA1 = pack2(t0.y, t1.x), TA2 = pack2(t0.z, t1.y);
    const u64 EB0 = pack2(e1.z, e2.y), EB1 = pack2(e1.w, e2.z), EB2 = pack2(e2.x, e2.w);
    const u64 TB0 = pack2(t1.z, t2.y), TB1 = pack2(t1.w, t2.z), TB2 = pack2(t2.x, t2.w);

    acc[0] = add2(acc[0], abs2(sub2(EA0, TA0)));
    acc[1] = add2(acc[1], abs2(sub2(EA0, TA1)));
    acc[2] = add2(acc[2], abs2(sub2(EA0, TA2)));
    acc[3] = add2(acc[3], abs2(sub2(EA1, TA0)));
    acc[4] = add2(acc[4], abs2(sub2(EA1, TA1)));
    acc[5] = add2(acc[5], abs2(sub2(EA1, TA2)));
    acc[6] = add2(acc[6], abs2(sub2(EA2, TA0)));
    acc[7] = add2(acc[7], abs2(sub2(EA2, TA1)));
    acc[8] = add2(acc[8], abs2(sub2(EA2, TA2)));

    acc[0] = add2(acc[0], abs2(sub2(EB0, TB0)));
    acc[1] = add2(acc[1], abs2(sub2(EB0, TB1)));
    acc[2] = add2(acc[2], abs2(sub2(EB0, TB2)));
    acc[3] = add2(acc[3], abs2(sub2(EB1, TB0)));
    acc[4] = add2(acc[4], abs2(sub2(EB1, TB1)));
    acc[5] = add2(acc[5], abs2(sub2(EB1, TB2)));
    acc[6] = add2(acc[6], abs2(sub2(EB2, TB0)));
    acc[7] = add2(acc[7], abs2(sub2(EB2, TB1)));
    acc[8] = add2(acc[8], abs2(sub2(EB2, TB2)));
}

__global__ void __launch_bounds__(NTHR) pil_tma_kernel(
    const float* __restrict__ est, const float* __restrict__ tgt,
    float* __restrict__ out)
{
    // 3-slot ring of SMEM tiles. 3 x 2 x 7296 = 43776 B.
    __shared__ __align__(128) float4 s_e[NSLOTS][STAGE_F4];
    __shared__ __align__(128) float4 s_t[NSLOTS][STAGE_F4];
    __shared__ __align__(8) unsigned long long s_full[NSLOTS];

    const int tid = threadIdx.x;
    const int b = blockIdx.x >> 4;        // batch
    const int x = blockIdx.x & 15;        // block-in-batch

    uint32_t full[NSLOTS], se[NSLOTS], st[NSLOTS];
#pragma unroll
    for (int s = 0; s < NSLOTS; s++) {
        full[s] = smem_u32(&s_full[s]);
        se[s]   = smem_u32(&s_e[s][0]);
        st[s]   = smem_u32(&s_t[s][0]);
    }

    if (tid == 0) {
#pragma unroll
        for (int s = 0; s < NSLOTS; s++) mbar_init(full[s], 1);
    }
    __syncthreads();
    asm volatile("fence.proxy.async.shared::cta;" ::: "memory");

    // This block's contiguous slice: QPB quads starting at x*QPB.
    const char* ge = (const char*)est + (size_t)b * NPB * 12 + (size_t)x * QPB * 48;
    const char* gt = (const char*)tgt + (size_t)b * NPB * 12 + (size_t)x * QPB * 48;

    // Prologue: fill slots 0 and 1.
    if (tid == 0) {
#pragma unroll
        for (int k = 0; k < 2; k++) {
            mbar_expect_tx(full[k], 2 * STAGE_B);
            tma_bulk_1d(se[k], ge + (size_t)k * STAGE_B, STAGE_B, full[k]);
            tma_bulk_1d(st[k], gt + (size_t)k * STAGE_B, STAGE_B, full[k]);
        }
    }

    u64 acc[9];
#pragma unroll
    for (int q = 0; q < 9; q++) acc[q] = 0ULL;

    for (int i = 0; i < NSTAGES; i++) {
        const int s = i % NSLOTS;

        // Issue stage i+2 FIRST: its slot was freed by the sync ending stage i-1,
        // so the TMA engine stays busy through this stage's consume+sync window.
        if (tid == 0) {
            const int k = i + 2;
            if (k < NSTAGES) {
                const int s2 = k % NSLOTS;
                mbar_expect_tx(full[s2], 2 * STAGE_B);
                tma_bulk_1d(se[s2], ge + (size_t)k * STAGE_B, STAGE_B, full[s2]);
                tma_bulk_1d(st[s2], gt + (size_t)k * STAGE_B, STAGE_B, full[s2]);
            }
        }

        // Wait for this stage's data; slot s completes its (i/3)-th fill here.
        mbar_wait(full[s], (i / NSLOTS) & 1);

        if (tid < QPS) {
            const float4* be = &s_e[s][3 * tid];
            const float4* bt = &s_t[s][3 * tid];
            accum_chunk(acc, be[0], be[1], be[2], bt[0], bt[1], bt[2]);
        }
        __syncthreads();   // slot s free for stage i+3's issue (top of iter i+1)
    }

    // Collapse packed halves.
    float a[9];
#pragma unroll
    for (int q = 0; q < 9; q++) {
        float lo, hi;
        unpack2(lo, hi, acc[q]);
        a[q] = lo + hi;
    }

    // Warp reduction (idle warps contribute zeros).
#pragma unroll
    for (int off = 16; off > 0; off >>= 1) {
#pragma unroll
        for (int q = 0; q < 9; q++)
            a[q] += __shfl_down_sync(0xFFFFFFFFu, a[q], off);
    }

    // Block reduction across 8 warps.
    __shared__ float s_part[NTHR / 32][9];
    const int lane = tid & 31;
    const int warp = tid >> 5;
    if (lane == 0) {
#pragma unroll
        for (int q = 0; q < 9; q++) s_part[warp][q] = a[q];
    }
    __syncthreads();

    if (tid < 9) {
        float s = 0.0f;
#pragma unroll
        for (int w = 0; w < NTHR / 32; w++) s += s_part[w][tid];
        atomicAdd(&g_C[b * 9 + tid], s);
    }

    // ---- hierarchical last-block-done ----
    __shared__ unsigned int s_islast;
    __threadfence();
    if (tid == 0) {
        s_islast = 0;
        if (atomicAdd(&g_cnt_b[b], 1u) == BLKX - 1) {
            __threadfence();
            s_islast = (atomicAdd(&g_cnt, 1u) == BB - 1);
        }
    }
    __syncthreads();
    if (!s_islast) return;

    // ---- finisher: permutation-min epilogue ----
    __shared__ float sC[BB * 9];
    for (int ent = tid; ent < BB * 9; ent += NTHR)
        sC[ent] = __ldcg(&g_C[ent]) * (1.0f / (float)NPB);
    __syncthreads();

    if (tid < 32) {
        const float* c = &sC[tid * 9];
        float best = c[0] + c[4] + c[8];
        best = fminf(best, c[0] + c[7] + c[5]);
        best = fminf(best, c[3] + c[1] + c[8]);
        best = fminf(best, c[3] + c[7] + c[2]);
        best = fminf(best, c[6] + c[1] + c[5]);
        best = fminf(best, c[6] + c[4] + c[2]);
        best *= (1.0f / 3.0f);

#pragma unroll
        for (int off = 16; off > 0; off >>= 1)
            best += __shfl_down_sync(0xFFFFFFFFu, best, off);

        if (tid == 0) out[0] = best * (1.0f / (float)BB);
    }
    __syncthreads();

    // Reset ALL scratch for the next graph replay.
    for (int ent = tid; ent < BB * 9; ent += NTHR) g_C[ent] = 0.0f;
    if (tid < BB) g_cnt_b[tid] = 0u;
    if (tid == 0) g_cnt = 0u;
}

extern "C" void kernel_launch(void* const* d_in, const int* in_sizes, int n_in,
                              void* d_out, int out_size) {
    const float* est = (const float*)d_in[0];
    const float* tgt = (const float*)d_in[1];
    float* out = (float*)d_out;

    pil_tma_kernel<<<NBLK, NTHR>>>(est, tgt, out);
}

// round 15
// speedup vs baseline: 1.4154x; 1.0616x over previous
#include <cuda_runtime.h>
#include <cstdint>

// Problem constants (B=32, T=512, F=513, S=3)
#define BB        32
#define NPB       262656            // triples per batch
#define NQUADS    65664             // NPB/4: quads (4 triples = 48B) per batch
#define BLKX      9                 // blocks per batch -> 288 CTAs (<=296 slots @2/SM)
#define NBLK      (BB * BLKX)       // 288
#define NTHR      256
#define QPB       (NQUADS / BLKX)   // 7296 quads per block
#define QPS       456               // quads per stage
#define NSTAGES   (QPB / QPS)       // 16, exact
#define STAGE_B   (QPS * 48)        // 21888 bytes per array per stage
#define STAGE_F4  (QPS * 3)         // 1368 float4 per array per stage
#define DYN_SMEM  (2 * 2 * STAGE_B) // 87552 B: 2 slots x (e,t)

typedef unsigned long long u64;

// Cost-matrix accumulators + hierarchical completion counters.
// Zero at static init; finisher re-zeroes everything -> graph-replay safe.
__device__ float g_C[BB * 9];
__device__ unsigned int g_cnt_b[BB];
__device__ unsigned int g_cnt;

__device__ __forceinline__ uint32_t smem_u32(const void* p) {
    uint32_t a;
    asm("{ .reg .u64 t; cvta.to.shared.u64 t, %1; cvt.u32.u64 %0, t; }" : "=r"(a) : "l"(p));
    return a;
}
__device__ __forceinline__ u64 pack2(float lo, float hi) {
    u64 r; asm("mov.b64 %0, {%1, %2};" : "=l"(r) : "f"(lo), "f"(hi)); return r;
}
__device__ __forceinline__ void unpack2(float& lo, float& hi, u64 a) {
    asm("mov.b64 {%0, %1}, %2;" : "=f"(lo), "=f"(hi) : "l"(a));
}
__device__ __forceinline__ u64 sub2(u64 a, u64 b) {
    u64 r; asm("sub.rn.f32x2 %0, %1, %2;" : "=l"(r) : "l"(a), "l"(b)); return r;
}
__device__ __forceinline__ u64 add2(u64 a, u64 b) {
    u64 r; asm("add.rn.f32x2 %0, %1, %2;" : "=l"(r) : "l"(a), "l"(b)); return r;
}
__device__ __forceinline__ u64 abs2(u64 a) { return a & 0x7FFFFFFF7FFFFFFFULL; }

__device__ __forceinline__ void mbar_init(uint32_t mbar, uint32_t cnt) {
    asm volatile("mbarrier.init.shared.b64 [%0], %1;" :: "r"(mbar), "r"(cnt) : "memory");
}
__device__ __forceinline__ void mbar_expect_tx(uint32_t mbar, uint32_t bytes) {
    asm volatile("mbarrier.arrive.expect_tx.shared.b64 _, [%0], %1;"
                 :: "r"(mbar), "r"(bytes) : "memory");
}
__device__ __forceinline__ void tma_bulk_1d(uint32_t smem_dst, const void* gmem_src,
                                            uint32_t bytes, uint32_t mbar) {
    asm volatile("cp.async.bulk.shared::cluster.global.mbarrier::complete_tx::bytes "
                 "[%0], [%1], %2, [%3];"
                 :: "r"(smem_dst), "l"(gmem_src), "r"(bytes), "r"(mbar) : "memory");
}
__device__ __forceinline__ void mbar_wait(uint32_t mbar, uint32_t parity) {
    asm volatile(
        "{\n\t"
        ".reg .pred P;\n\t"
        "WAIT_%=:\n\t"
        "mbarrier.try_wait.parity.acquire.cta.shared::cta.b64 P, [%0], %1, 0x989680;\n\t"
        "@P bra.uni DONE_%=;\n\t"
        "bra.uni WAIT_%=;\n\t"
        "DONE_%=:\n\t"
        "}"
        :: "r"(mbar), "r"(parity) : "memory");
}

// Accumulate one 12-float quad (3 float4 per array) into acc[9].
__device__ __forceinline__ void accum_chunk(
    u64* acc,
    const float4 e0, const float4 e1, const float4 e2,
    const float4 t0, const float4 t1, const float4 t2)
{
    const u64 EA0 = pack2(e0.x, e0.w), EA1 = pack2(e0.y, e1.x), EA2 = pack2(e0.z, e1.y);
    const u64 TA0 = pack2(t0.x, t0.w), TA1 = pack2(t0.y, t1.x), TA2 = pack2(t0.z, t1.y);
    const u64 EB0 = pack2(e1.z, e2.y), EB1 = pack2(e1.w, e2.z), EB2 = pack2(e2.x, e2.w);
    const u64 TB0 = pack2(t1.z, t2.y), TB1 = pack2(t1.w, t2.z), TB2 = pack2(t2.x, t2.w);

    acc[0] = add2(acc[0], abs2(sub2(EA0, TA0)));
    acc[1] = add2(acc[1], abs2(sub2(EA0, TA1)));
    acc[2] = add2(acc[2], abs2(sub2(EA0, TA2)));
    acc[3] = add2(acc[3], abs2(sub2(EA1, TA0)));
    acc[4] = add2(acc[4], abs2(sub2(EA1, TA1)));
    acc[5] = add2(acc[5], abs2(sub2(EA1, TA2)));
    acc[6] = add2(acc[6], abs2(sub2(EA2, TA0)));
    acc[7] = add2(acc[7], abs2(sub2(EA2, TA1)));
    acc[8] = add2(acc[8], abs2(sub2(EA2, TA2)));

    acc[0] = add2(acc[0], abs2(sub2(EB0, TB0)));
    acc[1] = add2(acc[1], abs2(sub2(EB0, TB1)));
    acc[2] = add2(acc[2], abs2(sub2(EB0, TB2)));
    acc[3] = add2(acc[3], abs2(sub2(EB1, TB0)));
    acc[4] = add2(acc[4], abs2(sub2(EB1, TB1)));
    acc[5] = add2(acc[5], abs2(sub2(EB1, TB2)));
    acc[6] = add2(acc[6], abs2(sub2(EB2, TB0)));
    acc[7] = add2(acc[7], abs2(sub2(EB2, TB1)));
    acc[8] = add2(acc[8], abs2(sub2(EB2, TB2)));
}

__global__ void __launch_bounds__(NTHR) pil_tma_kernel(
    const float* __restrict__ est, const float* __restrict__ tgt,
    float* __restrict__ out)
{
    // Dynamic SMEM: [slot0_e | slot0_t | slot1_e | slot1_t], 4 x 21888 B.
    extern __shared__ __align__(128) char dsmem[];
    float4* s_e[2];
    float4* s_t[2];
    s_e[0] = (float4*)(dsmem);
    s_t[0] = (float4*)(dsmem + STAGE_B);
    s_e[1] = (float4*)(dsmem + 2 * STAGE_B);
    s_t[1] = (float4*)(dsmem + 3 * STAGE_B);

    __shared__ __align__(8) unsigned long long s_full[2];

    const int tid = threadIdx.x;
    const int b = blockIdx.x / BLKX;      // batch
    const int x = blockIdx.x % BLKX;      // block-in-batch

    uint32_t full[2], se[2], st[2];
#pragma unroll
    for (int s = 0; s < 2; s++) {
        full[s] = smem_u32(&s_full[s]);
        se[s]   = smem_u32(s_e[s]);
        st[s]   = smem_u32(s_t[s]);
    }

    if (tid == 0) {
        mbar_init(full[0], 1);
        mbar_init(full[1], 1);
    }
    __syncthreads();
    asm volatile("fence.proxy.async.shared::cta;" ::: "memory");

    // This block's contiguous slice: QPB quads starting at x*QPB.
    const char* ge = (const char*)est + (size_t)b * NPB * 12 + (size_t)x * QPB * 48;
    const char* gt = (const char*)tgt + (size_t)b * NPB * 12 + (size_t)x * QPB * 48;

    // Prologue: fill both slots.
    if (tid == 0) {
#pragma unroll
        for (int k = 0; k < 2; k++) {
            mbar_expect_tx(full[k], 2 * STAGE_B);
            tma_bulk_1d(se[k], ge + (size_t)k * STAGE_B, STAGE_B, full[k]);
            tma_bulk_1d(st[k], gt + (size_t)k * STAGE_B, STAGE_B, full[k]);
        }
    }

    u64 acc[9];
#pragma unroll
    for (int q = 0; q < 9; q++) acc[q] = 0ULL;

    for (int i = 0; i < NSTAGES; i++) {
        const int s = i & 1;
        mbar_wait(full[s], (i >> 1) & 1);

        // 456 quads, 256 threads: thread t takes quads t and t+256 (if <456).
#pragma unroll
        for (int q = tid; q < QPS; q += NTHR) {
            const float4* be = &s_e[s][3 * q];
            const float4* bt = &s_t[s][3 * q];
            accum_chunk(acc, be[0], be[1], be[2], bt[0], bt[1], bt[2]);
        }
        __syncthreads();   // all consumers done with slot s

        if (tid == 0 && i + 2 < NSTAGES) {
            const size_t off = (size_t)(i + 2) * STAGE_B;
            mbar_expect_tx(full[s], 2 * STAGE_B);
            tma_bulk_1d(se[s], ge + off, STAGE_B, full[s]);
            tma_bulk_1d(st[s], gt + off, STAGE_B, full[s]);
        }
    }

    // Collapse packed halves.
    float a[9];
#pragma unroll
    for (int q = 0; q < 9; q++) {
        float lo, hi;
        unpack2(lo, hi, acc[q]);
        a[q] = lo + hi;
    }

    // Warp reduction.
#pragma unroll
    for (int off = 16; off > 0; off >>= 1) {
#pragma unroll
        for (int q = 0; q < 9; q++)
            a[q] += __shfl_down_sync(0xFFFFFFFFu, a[q], off);
    }

    // Block reduction across 8 warps.
    __shared__ float s_part[NTHR / 32][9];
    const int lane = tid & 31;
    const int warp = tid >> 5;
    if (lane == 0) {
#pragma unroll
        for (int q = 0; q < 9; q++) s_part[warp][q] = a[q];
    }
    __syncthreads();

    if (tid < 9) {
        float s = 0.0f;
#pragma unroll
        for (int w = 0; w < NTHR / 32; w++) s += s_part[w][tid];
        atomicAdd(&g_C[b * 9 + tid], s);
    }

    // ---- hierarchical last-block-done ----
    __shared__ unsigned int s_islast;
    __threadfence();
    if (tid == 0) {
        s_islast = 0;
        if (atomicAdd(&g_cnt_b[b], 1u) == BLKX - 1) {
            __threadfence();
            s_islast = (atomicAdd(&g_cnt, 1u) == BB - 1);
        }
    }
    __syncthreads();
    if (!s_islast) return;

    // ---- finisher: permutation-min epilogue ----
    __shared__ float sC[BB * 9];
    for (int ent = tid; ent < BB * 9; ent += NTHR)
        sC[ent] = __ldcg(&g_C[ent]) * (1.0f / (float)NPB);
    __syncthreads();

    if (tid < 32) {
        const float* c = &sC[tid * 9];
        float best = c[0] + c[4] + c[8];
        best = fminf(best, c[0] + c[7] + c[5]);
        best = fminf(best, c[3] + c[1] + c[8]);
        best = fminf(best, c[3] + c[7] + c[2]);
        best = fminf(best, c[6] + c[1] + c[5]);
        best = fminf(best, c[6] + c[4] + c[2]);
        best *= (1.0f / 3.0f);

#pragma unroll
        for (int off = 16; off > 0; off >>= 1)
            best += __shfl_down_sync(0xFFFFFFFFu, best, off);

        if (tid == 0) out[0] = best * (1.0f / (float)BB);
    }
    __syncthreads();

    // Reset ALL scratch for the next graph replay.
    for (int ent = tid; ent < BB * 9; ent += NTHR) g_C[ent] = 0.0f;
    if (tid < BB) g_cnt_b[tid] = 0u;
    if (tid == 0) g_cnt = 0u;
}

extern "C" void kernel_launch(void* const* d_in, const int* in_sizes, int n_in,
                              void* d_out, int out_size) {
    const float* est = (const float*)d_in[0];
    const float* tgt = (const float*)d_in[1];
    float* out = (float*)d_out;

    static bool attr_set = false;
    if (!attr_set) {
        cudaFuncSetAttribute(pil_tma_kernel,
                             cudaFuncAttributeMaxDynamicSharedMemorySize, DYN_SMEM);
        attr_set = true;
    }

    pil_tma_kernel<<<NBLK, NTHR, DYN_SMEM>>>(est, tgt, out);
}

// round 16
// speedup vs baseline: 1.5535x; 1.0975x over previous
#include <cuda_runtime.h>
#include <cstdint>

// Problem constants (B=32, T=512, F=513, S=3)
#define BB        32
#define NPB       262656            // triples per batch
#define NQUADS    65664             // NPB/4: quads (4 triples = 48B) per batch
#define BLKX      18                // blocks per batch -> 576 CTAs (97% of 592 slots @4/SM)
#define NBLK      (BB * BLKX)       // 576
#define NTHR      256
#define QPB       (NQUADS / BLKX)   // 3648 quads per block
#define QPS       228               // quads per stage (one per consuming thread)
#define NSTAGES   (QPB / QPS)       // 16, exact
#define STAGE_B   (QPS * 48)        // 10944 bytes per array per stage
#define STAGE_F4  (QPS * 3)         // 684 float4 per array per stage

typedef unsigned long long u64;

// Cost-matrix accumulators + hierarchical completion counters.
// Zero at static init; finisher re-zeroes everything -> graph-replay safe.
__device__ float g_C[BB * 9];
__device__ unsigned int g_cnt_b[BB];
__device__ unsigned int g_cnt;

__device__ __forceinline__ uint32_t smem_u32(const void* p) {
    uint32_t a;
    asm("{ .reg .u64 t; cvta.to.shared.u64 t, %1; cvt.u32.u64 %0, t; }" : "=r"(a) : "l"(p));
    return a;
}
__device__ __forceinline__ u64 pack2(float lo, float hi) {
    u64 r; asm("mov.b64 %0, {%1, %2};" : "=l"(r) : "f"(lo), "f"(hi)); return r;
}
__device__ __forceinline__ void unpack2(float& lo, float& hi, u64 a) {
    asm("mov.b64 {%0, %1}, %2;" : "=f"(lo), "=f"(hi) : "l"(a));
}
__device__ __forceinline__ u64 sub2(u64 a, u64 b) {
    u64 r; asm("sub.rn.f32x2 %0, %1, %2;" : "=l"(r) : "l"(a), "l"(b)); return r;
}
__device__ __forceinline__ u64 add2(u64 a, u64 b) {
    u64 r; asm("add.rn.f32x2 %0, %1, %2;" : "=l"(r) : "l"(a), "l"(b)); return r;
}
__device__ __forceinline__ u64 abs2(u64 a) { return a & 0x7FFFFFFF7FFFFFFFULL; }

__device__ __forceinline__ void mbar_init(uint32_t mbar, uint32_t cnt) {
    asm volatile("mbarrier.init.shared.b64 [%0], %1;" :: "r"(mbar), "r"(cnt) : "memory");
}
__device__ __forceinline__ void mbar_expect_tx(uint32_t mbar, uint32_t bytes) {
    asm volatile("mbarrier.arrive.expect_tx.shared.b64 _, [%0], %1;"
                 :: "r"(mbar), "r"(bytes) : "memory");
}
__device__ __forceinline__ void tma_bulk_1d(uint32_t smem_dst, const void* gmem_src,
                                            uint32_t bytes, uint32_t mbar) {
    asm volatile("cp.async.bulk.shared::cluster.global.mbarrier::complete_tx::bytes "
                 "[%0], [%1], %2, [%3];"
                 :: "r"(smem_dst), "l"(gmem_src), "r"(bytes), "r"(mbar) : "memory");
}
__device__ __forceinline__ void mbar_wait(uint32_t mbar, uint32_t parity) {
    asm volatile(
        "{\n\t"
        ".reg .pred P;\n\t"
        "WAIT_%=:\n\t"
        "mbarrier.try_wait.parity.acquire.cta.shared::cta.b64 P, [%0], %1, 0x989680;\n\t"
        "@P bra.uni DONE_%=;\n\t"
        "bra.uni WAIT_%=;\n\t"
        "DONE_%=:\n\t"
        "}"
        :: "r"(mbar), "r"(parity) : "memory");
}

// Accumulate one 12-float quad (3 float4 per array) into acc[9].
__device__ __forceinline__ void accum_chunk(
    u64* acc,
    const float4 e0, const float4 e1, const float4 e2,
    const float4 t0, const float4 t1, const float4 t2)
{
    const u64 EA0 = pack2(e0.x, e0.w), EA1 = pack2(e0.y, e1.x), EA2 = pack2(e0.z, e1.y);
    const u64 TA0 = pack2(t0.x, t0.w), TA1 = pack2(t0.y, t1.x), TA2 = pack2(t0.z, t1.y);
    const u64 EB0 = pack2(e1.z, e2.y), EB1 = pack2(e1.w, e2.z), EB2 = pack2(e2.x, e2.w);
    const u64 TB0 = pack2(t1.z, t2.y), TB1 = pack2(t1.w, t2.z), TB2 = pack2(t2.x, t2.w);

    acc[0] = add2(acc[0], abs2(sub2(EA0, TA0)));
    acc[1] = add2(acc[1], abs2(sub2(EA0, TA1)));
    acc[2] = add2(acc[2], abs2(sub2(EA0, TA2)));
    acc[3] = add2(acc[3], abs2(sub2(EA1, TA0)));
    acc[4] = add2(acc[4], abs2(sub2(EA1, TA1)));
    acc[5] = add2(acc[5], abs2(sub2(EA1, TA2)));
    acc[6] = add2(acc[6], abs2(sub2(EA2, TA0)));
    acc[7] = add2(acc[7], abs2(sub2(EA2, TA1)));
    acc[8] = add2(acc[8], abs2(sub2(EA2, TA2)));

    acc[0] = add2(acc[0], abs2(sub2(EB0, TB0)));
    acc[1] = add2(acc[1], abs2(sub2(EB0, TB1)));
    acc[2] = add2(acc[2], abs2(sub2(EB0, TB2)));
    acc[3] = add2(acc[3], abs2(sub2(EB1, TB0)));
    acc[4] = add2(acc[4], abs2(sub2(EB1, TB1)));
    acc[5] = add2(acc[5], abs2(sub2(EB1, TB2)));
    acc[6] = add2(acc[6], abs2(sub2(EB2, TB0)));
    acc[7] = add2(acc[7], abs2(sub2(EB2, TB1)));
    acc[8] = add2(acc[8], abs2(sub2(EB2, TB2)));
}

__global__ void __launch_bounds__(NTHR) pil_tma_kernel(
    const float* __restrict__ est, const float* __restrict__ tgt,
    float* __restrict__ out)
{
    // Double-buffered SMEM tiles (TMA destination). 2 x (10944 + 10944) = 43776 B.
    __shared__ __align__(128) float4 s_e[2][STAGE_F4];
    __shared__ __align__(128) float4 s_t[2][STAGE_F4];
    __shared__ __align__(8) unsigned long long s_full[2];

    const int tid = threadIdx.x;
    const int b = blockIdx.x / BLKX;      // batch
    const int x = blockIdx.x % BLKX;      // block-in-batch

    uint32_t full[2], se[2], st[2];
#pragma unroll
    for (int s = 0; s < 2; s++) {
        full[s] = smem_u32(&s_full[s]);
        se[s]   = smem_u32(&s_e[s][0]);
        st[s]   = smem_u32(&s_t[s][0]);
    }

    if (tid == 0) {
        mbar_init(full[0], 1);
        mbar_init(full[1], 1);
    }
    __syncthreads();
    asm volatile("fence.proxy.async.shared::cta;" ::: "memory");

    // This block's contiguous slice: QPB quads starting at x*QPB.
    const char* ge = (const char*)est + (size_t)b * NPB * 12 + (size_t)x * QPB * 48;
    const char* gt = (const char*)tgt + (size_t)b * NPB * 12 + (size_t)x * QPB * 48;

    // Prologue: fill both slots.
    if (tid == 0) {
#pragma unroll
        for (int k = 0; k < 2; k++) {
            mbar_expect_tx(full[k], 2 * STAGE_B);
            tma_bulk_1d(se[k], ge + (size_t)k * STAGE_B, STAGE_B, full[k]);
            tma_bulk_1d(st[k], gt + (size_t)k * STAGE_B, STAGE_B, full[k]);
        }
    }

    u64 acc[9];
#pragma unroll
    for (int q = 0; q < 9; q++) acc[q] = 0ULL;

    for (int i = 0; i < NSTAGES; i++) {
        const int s = i & 1;
        mbar_wait(full[s], (i >> 1) & 1);

        if (tid < QPS) {
            const float4* be = &s_e[s][3 * tid];
            const float4* bt = &s_t[s][3 * tid];
            accum_chunk(acc, be[0], be[1], be[2], bt[0], bt[1], bt[2]);
        }
        __syncthreads();   // everyone done with slot s before refill

        if (tid == 0 && i + 2 < NSTAGES) {
            const size_t off = (size_t)(i + 2) * STAGE_B;
            mbar_expect_tx(full[s], 2 * STAGE_B);
            tma_bulk_1d(se[s], ge + off, STAGE_B, full[s]);
            tma_bulk_1d(st[s], gt + off, STAGE_B, full[s]);
        }
    }

    // Collapse packed halves.
    float a[9];
#pragma unroll
    for (int q = 0; q < 9; q++) {
        float lo, hi;
        unpack2(lo, hi, acc[q]);
        a[q] = lo + hi;
    }

    // Warp reduction (idle threads contribute zeros).
#pragma unroll
    for (int off = 16; off > 0; off >>= 1) {
#pragma unroll
        for (int q = 0; q < 9; q++)
            a[q] += __shfl_down_sync(0xFFFFFFFFu, a[q], off);
    }

    // Block reduction across 8 warps.
    __shared__ float s_part[NTHR / 32][9];
    const int lane = tid & 31;
    const int warp = tid >> 5;
    if (lane == 0) {
#pragma unroll
        for (int q = 0; q < 9; q++) s_part[warp][q] = a[q];
    }
    __syncthreads();

    if (tid < 9) {
        float s = 0.0f;
#pragma unroll
        for (int w = 0; w < NTHR / 32; w++) s += s_part[w][tid];
        atomicAdd(&g_C[b * 9 + tid], s);
    }

    // ---- hierarchical last-block-done ----
    __shared__ unsigned int s_islast;
    __threadfence();
    if (tid == 0) {
        s_islast = 0;
        if (atomicAdd(&g_cnt_b[b], 1u) == BLKX - 1) {
            __threadfence();
            s_islast = (atomicAdd(&g_cnt, 1u) == BB - 1);
        }
    }
    __syncthreads();
    if (!s_islast) return;

    // ---- finisher: permutation-min epilogue ----
    __shared__ float sC[BB * 9];
    for (int ent = tid; ent < BB * 9; ent += NTHR)
        sC[ent] = __ldcg(&g_C[ent]) * (1.0f / (float)NPB);
    __syncthreads();

    if (tid < 32) {
        const float* c = &sC[tid * 9];
        float best = c[0] + c[4] + c[8];
        best = fminf(best, c[0] + c[7] + c[5]);
        best = fminf(best, c[3] + c[1] + c[8]);
        best = fminf(best, c[3] + c[7] + c[2]);
        best = fminf(best, c[6] + c[1] + c[5]);
        best = fminf(best, c[6] + c[4] + c[2]);
        best *= (1.0f / 3.0f);

#pragma unroll
        for (int off = 16; off > 0; off >>= 1)
            best += __shfl_down_sync(0xFFFFFFFFu, best, off);

        if (tid == 0) out[0] = best * (1.0f / (float)BB);
    }
    __syncthreads();

    // Reset ALL scratch for the next graph replay.
    for (int ent = tid; ent < BB * 9; ent += NTHR) g_C[ent] = 0.0f;
    if (tid < BB) g_cnt_b[tid] = 0u;
    if (tid == 0) g_cnt = 0u;
}

extern "C" void kernel_launch(void* const* d_in, const int* in_sizes, int n_in,
                              void* d_out, int out_size) {
    const float* est = (const float*)d_in[0];
    const float* tgt = (const float*)d_in[1];
    float* out = (float*)d_out;

    pil_tma_kernel<<<NBLK, NTHR>>>(est, tgt, out);
}

// round 17
// speedup vs baseline: 1.6346x; 1.0522x over previous
#include <cuda_runtime.h>
#include <cstdint>

// Problem constants (B=32, T=512, F=513, S=3)
#define BB        32
#define NPB       262656            // triples per batch
#define NQUADS    65664             // NPB/4: quads (4 triples = 48B) per batch
#define BLKX      16                // blocks per batch -> 512 CTAs (4/SM)
#define NBLK      (BB * BLKX)       // 512
#define NTHR      256
#define QPB       (NQUADS / BLKX)   // 4104 quads per block
#define TMA_QUADS 2052              // first half: TMA pipeline (warps 4-7)
#define LDG_QUADS 2052              // second half: direct LDG (warps 0-3)
#define QPS       228               // quads per TMA stage
#define NSTAGES   (TMA_QUADS / QPS) // 9, exact
#define STAGE_B   (QPS * 48)        // 10944 bytes per array per stage
#define STAGE_F4  (QPS * 3)         // 684 float4 per array per stage

typedef unsigned long long u64;

// Cost-matrix accumulators + hierarchical completion counters.
// Zero at static init; finisher re-zeroes everything -> graph-replay safe.
__device__ float g_C[BB * 9];
__device__ unsigned int g_cnt_b[BB];
__device__ unsigned int g_cnt;

__device__ __forceinline__ uint32_t smem_u32(const void* p) {
    uint32_t a;
    asm("{ .reg .u64 t; cvta.to.shared.u64 t, %1; cvt.u32.u64 %0, t; }" : "=r"(a) : "l"(p));
    return a;
}
__device__ __forceinline__ u64 pack2(float lo, float hi) {
    u64 r; asm("mov.b64 %0, {%1, %2};" : "=l"(r) : "f"(lo), "f"(hi)); return r;
}
__device__ __forceinline__ void unpack2(float& lo, float& hi, u64 a) {
    asm("mov.b64 {%0, %1}, %2;" : "=f"(lo), "=f"(hi) : "l"(a));
}
__device__ __forceinline__ u64 sub2(u64 a, u64 b) {
    u64 r; asm("sub.rn.f32x2 %0, %1, %2;" : "=l"(r) : "l"(a), "l"(b)); return r;
}
__device__ __forceinline__ u64 add2(u64 a, u64 b) {
    u64 r; asm("add.rn.f32x2 %0, %1, %2;" : "=l"(r) : "l"(a), "l"(b)); return r;
}
__device__ __forceinline__ u64 abs2(u64 a) { return a & 0x7FFFFFFF7FFFFFFFULL; }

__device__ __forceinline__ void mbar_init(uint32_t mbar, uint32_t cnt) {
    asm volatile("mbarrier.init.shared.b64 [%0], %1;" :: "r"(mbar), "r"(cnt) : "memory");
}
__device__ __forceinline__ void mbar_expect_tx(uint32_t mbar, uint32_t bytes) {
    asm volatile("mbarrier.arrive.expect_tx.shared.b64 _, [%0], %1;"
                 :: "r"(mbar), "r"(bytes) : "memory");
}
__device__ __forceinline__ void tma_bulk_1d(uint32_t smem_dst, const void* gmem_src,
                                            uint32_t bytes, uint32_t mbar) {
    asm volatile("cp.async.bulk.shared::cluster.global.mbarrier::complete_tx::bytes "
                 "[%0], [%1], %2, [%3];"
                 :: "r"(smem_dst), "l"(gmem_src), "r"(bytes), "r"(mbar) : "memory");
}
__device__ __forceinline__ void mbar_wait(uint32_t mbar, uint32_t parity) {
    asm volatile(
        "{\n\t"
        ".reg .pred P;\n\t"
        "WAIT_%=:\n\t"
        "mbarrier.try_wait.parity.acquire.cta.shared::cta.b64 P, [%0], %1, 0x989680;\n\t"
        "@P bra.uni DONE_%=;\n\t"
        "bra.uni WAIT_%=;\n\t"
        "DONE_%=:\n\t"
        "}"
        :: "r"(mbar), "r"(parity) : "memory");
}

// Accumulate one 12-float quad (3 float4 per array) into acc[9].
__device__ __forceinline__ void accum_chunk(
    u64* acc,
    const float4 e0, const float4 e1, const float4 e2,
    const float4 t0, const float4 t1, const float4 t2)
{
    const u64 EA0 = pack2(e0.x, e0.w), EA1 = pack2(e0.y, e1.x), EA2 = pack2(e0.z, e1.y);
    const u64 TA0 = pack2(t0.x, t0.w), TA1 = pack2(t0.y, t1.x), TA2 = pack2(t0.z, t1.y);
    const u64 EB0 = pack2(e1.z, e2.y), EB1 = pack2(e1.w, e2.z), EB2 = pack2(e2.x, e2.w);
    const u64 TB0 = pack2(t1.z, t2.y), TB1 = pack2(t1.w, t2.z), TB2 = pack2(t2.x, t2.w);

    acc[0] = add2(acc[0], abs2(sub2(EA0, TA0)));
    acc[1] = add2(acc[1], abs2(sub2(EA0, TA1)));
    acc[2] = add2(acc[2], abs2(sub2(EA0, TA2)));
    acc[3] = add2(acc[3], abs2(sub2(EA1, TA0)));
    acc[4] = add2(acc[4], abs2(sub2(EA1, TA1)));
    acc[5] = add2(acc[5], abs2(sub2(EA1, TA2)));
    acc[6] = add2(acc[6], abs2(sub2(EA2, TA0)));
    acc[7] = add2(acc[7], abs2(sub2(EA2, TA1)));
    acc[8] = add2(acc[8], abs2(sub2(EA2, TA2)));

    acc[0] = add2(acc[0], abs2(sub2(EB0, TB0)));
    acc[1] = add2(acc[1], abs2(sub2(EB0, TB1)));
    acc[2] = add2(acc[2], abs2(sub2(EB0, TB2)));
    acc[3] = add2(acc[3], abs2(sub2(EB1, TB0)));
    acc[4] = add2(acc[4], abs2(sub2(EB1, TB1)));
    acc[5] = add2(acc[5], abs2(sub2(EB1, TB2)));
    acc[6] = add2(acc[6], abs2(sub2(EB2, TB0)));
    acc[7] = add2(acc[7], abs2(sub2(EB2, TB1)));
    acc[8] = add2(acc[8], abs2(sub2(EB2, TB2)));
}

__global__ void __launch_bounds__(NTHR) pil_hybrid_kernel(
    const float* __restrict__ est, const float* __restrict__ tgt,
    float* __restrict__ out)
{
    // Double-buffered TMA tiles. 2 x 2 x 10944 = 43776 B.
    __shared__ __align__(128) float4 s_e[2][STAGE_F4];
    __shared__ __align__(128) float4 s_t[2][STAGE_F4];
    __shared__ __align__(8) unsigned long long s_full[2];

    const int tid = threadIdx.x;
    const int b = blockIdx.x >> 4;        // batch
    const int x = blockIdx.x & 15;        // block-in-batch

    uint32_t full[2], se[2], st[2];
#pragma unroll
    for (int s = 0; s < 2; s++) {
        full[s] = smem_u32(&s_full[s]);
        se[s]   = smem_u32(&s_e[s][0]);
        st[s]   = smem_u32(&s_t[s][0]);
    }

    if (tid == 0) {
        mbar_init(full[0], 1);
        mbar_init(full[1], 1);
    }
    __syncthreads();
    asm volatile("fence.proxy.async.shared::cta;" ::: "memory");

    // This block's contiguous slice: QPB quads at x*QPB within batch b.
    const char* ge = (const char*)est + (size_t)b * NPB * 12 + (size_t)x * QPB * 48;
    const char* gt = (const char*)tgt + (size_t)b * NPB * 12 + (size_t)x * QPB * 48;

    u64 acc[9];
#pragma unroll
    for (int q = 0; q < 9; q++) acc[q] = 0ULL;

    if (tid >= 128) {
        // ===== TMA half: warps 4-7 stream quads [0, TMA_QUADS) via SMEM =====
        const int wtid = tid - 128;

        if (tid == 128) {   // producer-elect: prologue fills both slots
#pragma unroll
            for (int k = 0; k < 2; k++) {
                mbar_expect_tx(full[k], 2 * STAGE_B);
                tma_bulk_1d(se[k], ge + (size_t)k * STAGE_B, STAGE_B, full[k]);
                tma_bulk_1d(st[k], gt + (size_t)k * STAGE_B, STAGE_B, full[k]);
            }
        }

        for (int i = 0; i < NSTAGES; i++) {
            const int s = i & 1;
            mbar_wait(full[s], (i >> 1) & 1);

            // 228 quads over 128 threads (1-2 each).
            for (int q = wtid; q < QPS; q += 128) {
                const float4* be = &s_e[s][3 * q];
                const float4* bt = &s_t[s][3 * q];
                accum_chunk(acc, be[0], be[1], be[2], bt[0], bt[1], bt[2]);
            }
            asm volatile("bar.sync 1, 128;" ::: "memory");  // TMA warps only

            if (tid == 128 && i + 2 < NSTAGES) {
                const size_t off = (size_t)(i + 2) * STAGE_B;
                mbar_expect_tx(full[s], 2 * STAGE_B);
                tma_bulk_1d(se[s], ge + off, STAGE_B, full[s]);
                tma_bulk_1d(st[s], gt + off, STAGE_B, full[s]);
            }
        }
    } else {
        // ===== LDG half: warps 0-3 stream quads [TMA_QUADS, QPB) directly =====
        const float4* e4 = (const float4*)(ge + (size_t)TMA_QUADS * 48);
        const float4* t4 = (const float4*)(gt + (size_t)TMA_QUADS * 48);

        int m = tid;   // 0..127
        // Unroll-by-2: 12 front-batched LDG.128 per iteration.
        for (; m + 128 < LDG_QUADS; m += 256) {
            const int m2 = m + 128;
            const float4 ea0 = __ldcs(&e4[3 * m + 0]);
            const float4 ea1 = __ldcs(&e4[3 * m + 1]);
            const float4 ea2 = __ldcs(&e4[3 * m + 2]);
            const float4 ta0 = __ldcs(&t4[3 * m + 0]);
            const float4 ta1 = __ldcs(&t4[3 * m + 1]);
            const float4 ta2 = __ldcs(&t4[3 * m + 2]);
            const float4 eb0 = __ldcs(&e4[3 * m2 + 0]);
            const float4 eb1 = __ldcs(&e4[3 * m2 + 1]);
            const float4 eb2 = __ldcs(&e4[3 * m2 + 2]);
            const float4 tb0 = __ldcs(&t4[3 * m2 + 0]);
            const float4 tb1 = __ldcs(&t4[3 * m2 + 1]);
            const float4 tb2 = __ldcs(&t4[3 * m2 + 2]);
            accum_chunk(acc, ea0, ea1, ea2, ta0, ta1, ta2);
            accum_chunk(acc, eb0, eb1, eb2, tb0, tb1, tb2);
        }
        for (; m < LDG_QUADS; m += 128) {
            const float4 e0 = __ldcs(&e4[3 * m + 0]);
            const float4 e1 = __ldcs(&e4[3 * m + 1]);
            const float4 e2 = __ldcs(&e4[3 * m + 2]);
            const float4 t0 = __ldcs(&t4[3 * m + 0]);
            const float4 t1 = __ldcs(&t4[3 * m + 1]);
            const float4 t2 = __ldcs(&t4[3 * m + 2]);
            accum_chunk(acc, e0, e1, e2, t0, t1, t2);
        }
    }

    // Collapse packed halves.
    float a[9];
#pragma unroll
    for (int q = 0; q < 9; q++) {
        float lo, hi;
        unpack2(lo, hi, acc[q]);
        a[q] = lo + hi;
    }

    // Warp reduction.
#pragma unroll
    for (int off = 16; off > 0; off >>= 1) {
#pragma unroll
        for (int q = 0; q < 9; q++)
            a[q] += __shfl_down_sync(0xFFFFFFFFu, a[q], off);
    }

    // Block reduction across 8 warps.
    __shared__ float s_part[NTHR / 32][9];
    const int lane = tid & 31;
    const int warp = tid >> 5;
    if (lane == 0) {
#pragma unroll
        for (int q = 0; q < 9; q++) s_part[warp][q] = a[q];
    }
    __syncthreads();

    if (tid < 9) {
        float s = 0.0f;
#pragma unroll
        for (int w = 0; w < NTHR / 32; w++) s += s_part[w][tid];
        atomicAdd(&g_C[b * 9 + tid], s);
    }

    // ---- hierarchical last-block-done ----
    __shared__ unsigned int s_islast;
    __threadfence();
    if (tid == 0) {
        s_islast = 0;
        if (atomicAdd(&g_cnt_b[b], 1u) == BLKX - 1) {
            __threadfence();
            s_islast = (atomicAdd(&g_cnt, 1u) == BB - 1);
        }
    }
    __syncthreads();
    if (!s_islast) return;

    // ---- finisher: permutation-min epilogue ----
    __shared__ float sC[BB * 9];
    for (int ent = tid; ent < BB * 9; ent += NTHR)
        sC[ent] = __ldcg(&g_C[ent]) * (1.0f / (float)NPB);
    __syncthreads();

    if (tid < 32) {
        const float* c = &sC[tid * 9];
        float best = c[0] + c[4] + c[8];
        best = fminf(best, c[0] + c[7] + c[5]);
        best = fminf(best, c[3] + c[1] + c[8]);
        best = fminf(best, c[3] + c[7] + c[2]);
        best = fminf(best, c[6] + c[1] + c[5]);
        best = fminf(best, c[6] + c[4] + c[2]);
        best *= (1.0f / 3.0f);

#pragma unroll
        for (int off = 16; off > 0; off >>= 1)
            best += __shfl_down_sync(0xFFFFFFFFu, best, off);

        if (tid == 0) out[0] = best * (1.0f / (float)BB);
    }
    __syncthreads();

    // Reset ALL scratch for the next graph replay.
    for (int ent = tid; ent < BB * 9; ent += NTHR) g_C[ent] = 0.0f;
    if (tid < BB) g_cnt_b[tid] = 0u;
    if (tid == 0) g_cnt = 0u;
}

extern "C" void kernel_launch(void* const* d_in, const int* in_sizes, int n_in,
                              void* d_out, int out_size) {
    const float* est = (const float*)d_in[0];
    const float* tgt = (const float*)d_in[1];
    float* out = (float*)d_out;

    pil_hybrid_kernel<<<NBLK, NTHR>>>(est, tgt, out);
}